// round 3
// baseline (speedup 1.0000x reference)
#include <cuda_runtime.h>
#include <cstddef>

#define D 256
#define NB 30
#define BGR 2048
#define NNODES (BGR * NB)      // 61440
#define EPG 240
#define NEDGES (BGR * EPG)     // 491520

// Scratch (device globals: allocation-free rule)
__device__ float g_bufA[(size_t)NNODES * 512];  // rows: [x | Smean]
__device__ float g_bufB[(size_t)NNODES * 512];
__device__ float g_cnt[NNODES];
__device__ float g_gvec[(size_t)BGR * 1024];    // [g0|g1|g2|g3] per graph
__device__ float g_latent[(size_t)BGR * D];
__device__ float g_Wg[5 * D];                   // W_geo @ W_lot[0:256]
__device__ float g_emb2[11 * D];                // emb @ W_lot[256:512]
__device__ float g_biasT[D];                    // b_lot + b_geo @ W_lot[0:256]

// ---------------------------------------------------------------------------
// Fold the input MLP: small weight-fusion GEMMs (17 rows x 256 cols, K=256)
// ---------------------------------------------------------------------------
__global__ void precompute_k(const float* __restrict__ Wgeo,
                             const float* __restrict__ bgeo,
                             const float* __restrict__ emb,
                             const float* __restrict__ Wlot,
                             const float* __restrict__ blot) {
    int row = blockIdx.x;        // 0..4: Wg rows; 5..15: emb2 rows; 16: biasT
    int c = threadIdx.x;
    float acc = 0.f;
    if (row < 5) {
        for (int j = 0; j < D; j++) acc += Wgeo[row * D + j] * Wlot[j * D + c];
        g_Wg[row * D + c] = acc;
    } else if (row < 16) {
        int s = row - 5;
        for (int j = 0; j < D; j++) acc += emb[s * D + j] * Wlot[(256 + j) * D + c];
        g_emb2[s * D + c] = acc;
    } else {
        for (int j = 0; j < D; j++) acc += bgeo[j] * Wlot[j * D + c];
        g_biasT[c] = acc + blot[c];
    }
}

// ---------------------------------------------------------------------------
// h0 = relu(geometry@Wg + emb2[sem] + Wpos[pos] + biasT)  -> bufA left half
// ---------------------------------------------------------------------------
__global__ void node_init_k(const float* __restrict__ geom,
                            const int* __restrict__ sem,
                            const float* __restrict__ Wlot) {
    int node = blockIdx.x;
    int c = threadIdx.x;
    int pos = node % NB;
    int s = sem[node];
    float acc = g_biasT[c] + g_emb2[s * D + c] + Wlot[(512 + pos) * D + c];
#pragma unroll
    for (int k = 0; k < 5; k++) acc += geom[node * 5 + k] * g_Wg[k * D + c];
    g_bufA[(size_t)node * 512 + c] = fmaxf(acc, 0.f);
}

// ---------------------------------------------------------------------------
// Per-graph segment max over 30 rows (reads left half of a buf)
// ---------------------------------------------------------------------------
__global__ void segmax_k(const float* __restrict__ buf, int phase) {
    int b = blockIdx.x;
    int c = threadIdx.x;
    const float* p = buf + (size_t)b * NB * 512 + c;
    float m = -1e30f;
#pragma unroll
    for (int r = 0; r < NB; r++) m = fmaxf(m, p[(size_t)r * 512]);
    g_gvec[(size_t)b * 1024 + phase * D + c] = m;
}

// ---------------------------------------------------------------------------
// Neighbor mean gather: one block per graph, thread t owns column t.
// Writes Smean into the right half of the SAME buffer, cnt to g_cnt.
// ---------------------------------------------------------------------------
__global__ void gather_k(float* __restrict__ buf,
                         const int* __restrict__ esrc,
                         const int* __restrict__ edst) {
    __shared__ float S[NB * D];          // 30 KB
    __shared__ int e_s[EPG], e_d[EPG];
    __shared__ float cnt_s[NB];
    int b = blockIdx.x;
    int t = threadIdx.x;

    for (int i = t; i < NB * D; i += 256) S[i] = 0.f;
    if (t < NB) cnt_s[t] = 0.f;
    __syncthreads();
    if (t < EPG) {
        int s = esrc[(size_t)b * EPG + t] - b * NB;
        int d0 = edst[(size_t)b * EPG + t] - b * NB;
        e_s[t] = s;
        e_d[t] = d0;
        atomicAdd(&cnt_s[d0], 1.f);
    }
    __syncthreads();

    const float* hb = buf + (size_t)b * NB * 512;
#pragma unroll 8
    for (int e = 0; e < EPG; e++) {
        int s = e_s[e], d0 = e_d[e];
        S[d0 * D + t] += hb[(size_t)s * 512 + t];   // column-owned: no races
    }
    // no sync needed: thread t only touched column t of S
    for (int r = 0; r < NB; r++) {
        float c = cnt_s[r];
        float v = (c > 0.f) ? S[r * D + t] / c : 0.f;
        buf[((size_t)b * NB + r) * 512 + 256 + t] = v;
    }
    if (t < NB) g_cnt[b * NB + t] = cnt_s[t];
}

// ---------------------------------------------------------------------------
// SGEMM: C[M,N(tile)] = A[M,K](lda) @ B[K,N] + bias  (+relu, +cnt mask)
// 128x128 tile, BK=8, 256 threads, 8x8 per thread.
// Grid: (N/128, M/128). All dims are multiples of 128/8 in this problem.
// ---------------------------------------------------------------------------
template <int RELU, int MASK>
__global__ void sgemm_k(const float* __restrict__ A, int lda,
                        const float* __restrict__ B, int N, int K,
                        const float* __restrict__ bias,
                        float* __restrict__ C, int ldc,
                        const float* __restrict__ mask) {
    __shared__ float As[8][128];
    __shared__ float Bs[8][128];
    int tid = threadIdx.x;
    int brow = blockIdx.y * 128;
    int bcol = blockIdx.x * 128;

    int a_r = tid >> 1;            // 0..127
    int a_c = (tid & 1) * 4;       // 0 or 4
    int b_r = tid >> 5;            // 0..7
    int b_c = (tid & 31) * 4;      // 0..124
    int ty = tid >> 4, tx = tid & 15;

    float acc[8][8] = {};
    const float* Aptr = A + (size_t)(brow + a_r) * lda + a_c;
    const float* Bptr = B + (size_t)b_r * N + bcol + b_c;

    for (int k0 = 0; k0 < K; k0 += 8) {
        float4 av = *(const float4*)(Aptr + k0);
        float4 bv = *(const float4*)(Bptr + (size_t)k0 * N);
        As[a_c + 0][a_r] = av.x;
        As[a_c + 1][a_r] = av.y;
        As[a_c + 2][a_r] = av.z;
        As[a_c + 3][a_r] = av.w;
        *(float4*)&Bs[b_r][b_c] = bv;
        __syncthreads();
#pragma unroll
        for (int k = 0; k < 8; k++) {
            float ar[8], br[8];
            *(float4*)(ar) = *(const float4*)&As[k][ty * 8];
            *(float4*)(ar + 4) = *(const float4*)&As[k][ty * 8 + 4];
            *(float4*)(br) = *(const float4*)&Bs[k][tx * 8];
            *(float4*)(br + 4) = *(const float4*)&Bs[k][tx * 8 + 4];
#pragma unroll
            for (int i = 0; i < 8; i++)
#pragma unroll
                for (int j = 0; j < 8; j++) acc[i][j] += ar[i] * br[j];
        }
        __syncthreads();
    }

    float4 bv0 = *(const float4*)&bias[bcol + tx * 8];
    float4 bv1 = *(const float4*)&bias[bcol + tx * 8 + 4];
#pragma unroll
    for (int i = 0; i < 8; i++) {
        int r = brow + ty * 8 + i;
        float keep = 1.f;
        if (MASK) keep = (mask[r] > 0.f) ? 1.f : 0.f;
        float4 v0, v1;
        v0.x = acc[i][0] + bv0.x; v0.y = acc[i][1] + bv0.y;
        v0.z = acc[i][2] + bv0.z; v0.w = acc[i][3] + bv0.w;
        v1.x = acc[i][4] + bv1.x; v1.y = acc[i][5] + bv1.y;
        v1.z = acc[i][6] + bv1.z; v1.w = acc[i][7] + bv1.w;
        if (RELU) {
            v0.x = fmaxf(v0.x, 0.f); v0.y = fmaxf(v0.y, 0.f);
            v0.z = fmaxf(v0.z, 0.f); v0.w = fmaxf(v0.w, 0.f);
            v1.x = fmaxf(v1.x, 0.f); v1.y = fmaxf(v1.y, 0.f);
            v1.z = fmaxf(v1.z, 0.f); v1.w = fmaxf(v1.w, 0.f);
        }
        if (MASK) {
            v0.x *= keep; v0.y *= keep; v0.z *= keep; v0.w *= keep;
            v1.x *= keep; v1.y *= keep; v1.z *= keep; v1.w *= keep;
        }
        *(float4*)&C[(size_t)r * ldc + bcol + tx * 8] = v0;
        *(float4*)&C[(size_t)r * ldc + bcol + tx * 8 + 4] = v1;
    }
}

extern "C" void kernel_launch(void* const* d_in, const int* in_sizes, int n_in,
                              void* d_out, int out_size) {
    (void)in_sizes; (void)n_in; (void)out_size;
    const float* geometry = (const float*)d_in[0];
    const int*   semantic = (const int*)d_in[1];
    const int*   edge_index = (const int*)d_in[2];
    // d_in[3] = batch (unused: batch[i] == i / NB by construction)
    const float* W_geo = (const float*)d_in[4];
    const float* b_geo = (const float*)d_in[5];
    const float* emb   = (const float*)d_in[6];
    const float* W_lot = (const float*)d_in[7];
    const float* b_lot = (const float*)d_in[8];
    const float* W_mp[3] = {(const float*)d_in[9], (const float*)d_in[11], (const float*)d_in[13]};
    const float* b_mp[3] = {(const float*)d_in[10], (const float*)d_in[12], (const float*)d_in[14]};
    const float* W_agg = (const float*)d_in[15];
    const float* b_agg = (const float*)d_in[16];
    const float* W_mu  = (const float*)d_in[17];
    const float* b_mu  = (const float*)d_in[18];
    const float* W_var = (const float*)d_in[19];
    const float* b_var = (const float*)d_in[20];
    float* out = (float*)d_out;

    float *bufA, *bufB, *cnt, *gvec, *latent;
    cudaGetSymbolAddress((void**)&bufA, g_bufA);
    cudaGetSymbolAddress((void**)&bufB, g_bufB);
    cudaGetSymbolAddress((void**)&cnt, g_cnt);
    cudaGetSymbolAddress((void**)&gvec, g_gvec);
    cudaGetSymbolAddress((void**)&latent, g_latent);

    const int* esrc = edge_index;
    const int* edst = edge_index + NEDGES;

    precompute_k<<<17, 256>>>(W_geo, b_geo, emb, W_lot, b_lot);
    node_init_k<<<NNODES, 256>>>(geometry, semantic, W_lot);
    segmax_k<<<BGR, 256>>>(bufA, 0);

    float* bufs[2] = {bufA, bufB};
    for (int r = 0; r < 3; r++) {
        float* ibuf = bufs[r & 1];
        float* obuf = bufs[(r + 1) & 1];
        gather_k<<<BGR, 256>>>(ibuf, esrc, edst);
        sgemm_k<1, 1><<<dim3(2, NNODES / 128), 256>>>(
            ibuf, 512, W_mp[r], 256, 512, b_mp[r], obuf, 512, cnt);
        segmax_k<<<BGR, 256>>>(obuf, r + 1);
    }

    // head: latent = g @ W_agg + b_agg ; mu / log_var
    sgemm_k<0, 0><<<dim3(2, BGR / 128), 256>>>(gvec, 1024, W_agg, 256, 1024,
                                               b_agg, latent, 256, nullptr);
    sgemm_k<0, 0><<<dim3(2, BGR / 128), 256>>>(latent, 256, W_mu, 256, 256,
                                               b_mu, out, 256, nullptr);
    sgemm_k<0, 0><<<dim3(2, BGR / 128), 256>>>(latent, 256, W_var, 256, 256,
                                               b_var, out + (size_t)BGR * D, 256, nullptr);
}

// round 6
// speedup vs baseline: 1.9129x; 1.9129x over previous
#include <cuda_runtime.h>
#include <cuda_bf16.h>
#include <cstdint>
#include <cstddef>

#define D 256
#define NB 30
#define BGR 2048
#define NNODES (BGR * NB)      // 61440
#define EPG 240
#define NEDGES (BGR * EPG)     // 491520

// ---------------- device scratch (allocation-free rule) ----------------
__device__ float g_h[(size_t)NNODES * D];        // current node features fp32
__device__ __nv_bfloat16 g_Ah[(size_t)NNODES * 512];  // split-bf16 GEMM A operand
__device__ __nv_bfloat16 g_Al[(size_t)NNODES * 512];
__device__ float g_cnt[NNODES];
__device__ float g_gvec[(size_t)BGR * 1024];     // [g0|g1|g2|g3]
__device__ float g_latent[(size_t)BGR * D];
__device__ float g_Wg[5 * D];
__device__ float g_emb2[11 * D];
__device__ float g_biasT[D];
// split-bf16 transposed msgpass weights: [3][N=256][K=512]
__device__ __nv_bfloat16 g_Wth[3 * 256 * 512];
__device__ __nv_bfloat16 g_Wtl[3 * 256 * 512];

// ---------------- helpers ----------------
__device__ __forceinline__ uint32_t smem_u32(const void* p) {
    uint32_t a;
    asm("{ .reg .u64 t; cvta.to.shared.u64 t, %1; cvt.u32.u64 %0, t; }" : "=r"(a) : "l"(p));
    return a;
}

#define LDSM(r, addr) \
    asm volatile("ldmatrix.sync.aligned.m8n8.x4.shared.b16 {%0,%1,%2,%3}, [%4];" \
        : "=r"((r)[0]), "=r"((r)[1]), "=r"((r)[2]), "=r"((r)[3]) : "r"(addr))

#define MMA(d, a, b0_, b1_) \
    asm volatile("mma.sync.aligned.m16n8k16.row.col.f32.bf16.bf16.f32 " \
        "{%0,%1,%2,%3}, {%4,%5,%6,%7}, {%8,%9}, {%0,%1,%2,%3};" \
        : "+f"((d)[0]), "+f"((d)[1]), "+f"((d)[2]), "+f"((d)[3]) \
        : "r"((a)[0]), "r"((a)[1]), "r"((a)[2]), "r"((a)[3]), "r"(b0_), "r"(b1_))

// ---------------------------------------------------------------------------
// Fold input MLP weights
// ---------------------------------------------------------------------------
__global__ void precompute_k(const float* __restrict__ Wgeo,
                             const float* __restrict__ bgeo,
                             const float* __restrict__ emb,
                             const float* __restrict__ Wlot,
                             const float* __restrict__ blot) {
    int row = blockIdx.x;
    int c = threadIdx.x;
    float acc = 0.f;
    if (row < 5) {
        for (int j = 0; j < D; j++) acc += Wgeo[row * D + j] * Wlot[j * D + c];
        g_Wg[row * D + c] = acc;
    } else if (row < 16) {
        int s = row - 5;
        for (int j = 0; j < D; j++) acc += emb[s * D + j] * Wlot[(256 + j) * D + c];
        g_emb2[s * D + c] = acc;
    } else {
        for (int j = 0; j < D; j++) acc += bgeo[j] * Wlot[j * D + c];
        g_biasT[c] = acc + blot[c];
    }
}

// ---------------------------------------------------------------------------
// Split + transpose msgpass weights: Wt[n][k] = W[k][n] as bf16 hi/lo
// ---------------------------------------------------------------------------
__global__ void wsplit_k(const float* __restrict__ W0,
                         const float* __restrict__ W1,
                         const float* __restrict__ W2) {
    int e = blockIdx.x * 256 + threadIdx.x;          // 3*131072 total
    int m = e / 131072;
    int r = e % 131072;
    int n = r >> 9, k = r & 511;
    const float* W = (m == 0) ? W0 : (m == 1) ? W1 : W2;
    float v = W[k * 256 + n];
    __nv_bfloat16 hi = __float2bfloat16(v);
    __nv_bfloat16 lo = __float2bfloat16(v - __bfloat162float(hi));
    g_Wth[(size_t)m * 131072 + n * 512 + k] = hi;
    g_Wtl[(size_t)m * 131072 + n * 512 + k] = lo;
}

// ---------------------------------------------------------------------------
// h0 = relu(geometry@Wg + emb2[sem] + Wpos[pos] + biasT)
// ---------------------------------------------------------------------------
__global__ void node_init_k(const float* __restrict__ geom,
                            const int* __restrict__ sem,
                            const float* __restrict__ Wlot) {
    int node = blockIdx.x;
    int c = threadIdx.x;
    int pos = node % NB;
    int s = sem[node];
    float acc = g_biasT[c] + g_emb2[s * D + c] + Wlot[(512 + pos) * D + c];
#pragma unroll
    for (int k = 0; k < 5; k++) acc += geom[node * 5 + k] * g_Wg[k * D + c];
    g_h[(size_t)node * D + c] = fmaxf(acc, 0.f);
}

// ---------------------------------------------------------------------------
// Standalone segmax (final phase)
// ---------------------------------------------------------------------------
__global__ void segmax_k(const float* __restrict__ h, int phase) {
    int b = blockIdx.x;
    int c = threadIdx.x;
    const float* p = h + (size_t)b * NB * D + c;
    float m = -1e30f;
#pragma unroll
    for (int r = 0; r < NB; r++) m = fmaxf(m, p[(size_t)r * D]);
    g_gvec[(size_t)b * 1024 + phase * D + c] = m;
}

// ---------------------------------------------------------------------------
// Fused gather + segmax + split-bf16 operand production.
// Left half of A row = split(h); right half = split(neighbor mean).
// ---------------------------------------------------------------------------
__global__ void gather_seg_k(const float* __restrict__ h,
                             __nv_bfloat16* __restrict__ Ah,
                             __nv_bfloat16* __restrict__ Al,
                             const int* __restrict__ esrc,
                             const int* __restrict__ edst,
                             int phase) {
    __shared__ float hb[NB * D];     // 30 KB
    __shared__ float cnt_s[NB], inv_s[NB];
    __shared__ int start_s[NB + 1], pos_s[NB];
    __shared__ int srt[EPG], ed_s[EPG], ed_d[EPG];
    int b = blockIdx.x, t = threadIdx.x;

    const float* base = h + (size_t)b * NB * D + t;
    float m = -1e30f;
#pragma unroll
    for (int r = 0; r < NB; r++) {
        float v = base[(size_t)r * D];
        hb[r * D + t] = v;
        m = fmaxf(m, v);
        __nv_bfloat16 hi = __float2bfloat16(v);
        __nv_bfloat16 lo = __float2bfloat16(v - __bfloat162float(hi));
        size_t row = (size_t)(b * NB + r) * 512;
        Ah[row + t] = hi;
        Al[row + t] = lo;
    }
    g_gvec[(size_t)b * 1024 + phase * D + t] = m;
    if (t < NB) cnt_s[t] = 0.f;
    __syncthreads();
    if (t < EPG) {
        int s = esrc[(size_t)b * EPG + t] - b * NB;
        int d0 = edst[(size_t)b * EPG + t] - b * NB;
        ed_s[t] = s;
        ed_d[t] = d0;
        atomicAdd(&cnt_s[d0], 1.f);
    }
    __syncthreads();
    if (t == 0) {
        int acc = 0;
        for (int r = 0; r < NB; r++) {
            start_s[r] = acc;
            pos_s[r] = acc;
            acc += (int)cnt_s[r];
        }
        start_s[NB] = acc;
    }
    __syncthreads();
    if (t < EPG) {
        int idx = atomicAdd(&pos_s[ed_d[t]], 1);
        srt[idx] = ed_s[t];
    }
    if (t < NB) {
        float c = cnt_s[t];
        inv_s[t] = (c > 0.f) ? 1.f / c : 0.f;
        g_cnt[b * NB + t] = c;
    }
    __syncthreads();

    for (int r = 0; r < NB; r++) {
        float acc = 0.f;
        int e0 = start_s[r], e1 = start_s[r + 1];
        for (int j = e0; j < e1; j++) acc += hb[srt[j] * D + t];
        float v = acc * inv_s[r];
        __nv_bfloat16 hi = __float2bfloat16(v);
        __nv_bfloat16 lo = __float2bfloat16(v - __bfloat162float(hi));
        size_t row = (size_t)(b * NB + r) * 512;
        Ah[row + 256 + t] = hi;
        Al[row + 256 + t] = lo;
    }
}

// ---------------------------------------------------------------------------
// Split-bf16 tensor-core GEMM via mma.sync:
//   C[61440,256] = mask * relu(A[61440,512] @ Wt^T + bias)
// CTA: 128 M x 256 N, 8 warps of 64x64, K chunked by 64 through smem.
// 3 mma products per tile: Ah*Wh + Al*Wh + Ah*Wl.
// ---------------------------------------------------------------------------
#define KC 64
#define RSTRIDE 144                 // 128B row + 16B pad (conflict-free ldmatrix)
#define S_AH 0
#define S_AL (128 * RSTRIDE)        // 18432
#define S_WH (2 * 128 * RSTRIDE)    // 36864
#define S_WL (S_WH + 256 * RSTRIDE) // 73728
#define S_TOTAL (S_WL + 256 * RSTRIDE) // 110592

__global__ void __launch_bounds__(256, 1)
mma_gemm_k(const __nv_bfloat16* __restrict__ Ah,
           const __nv_bfloat16* __restrict__ Al,
           const __nv_bfloat16* __restrict__ Wh,
           const __nv_bfloat16* __restrict__ Wl,
           const float* __restrict__ bias,
           const float* __restrict__ cnt,
           float* __restrict__ C) {
    extern __shared__ char smem[];
    uint32_t sb = smem_u32(smem);
    int tid = threadIdx.x;
    int lane = tid & 31, wid = tid >> 5;
    int brow = blockIdx.x * 128;
    int wm = wid & 1;          // M warp (2)
    int wn = wid >> 1;         // N warp (4)

    float acc[4][8][4];
#pragma unroll
    for (int i = 0; i < 4; i++)
#pragma unroll
        for (int j = 0; j < 8; j++)
#pragma unroll
            for (int q = 0; q < 4; q++) acc[i][j][q] = 0.f;

    // per-lane ldmatrix base addresses
    uint32_t aBase = sb + S_AH +
        (uint32_t)((wm * 64 + (lane & 15)) * RSTRIDE + (lane >> 4) * 16);
    int bq = lane >> 3;
    uint32_t bBase = sb + S_WH +
        (uint32_t)((wn * 64 + (lane & 7) + (bq & 2) * 4) * RSTRIDE + (bq & 1) * 16);

    for (int chunk = 0; chunk < 8; chunk++) {
        int k0 = chunk * KC;
        __syncthreads();
        // stage A hi/lo: 128 rows x 64 bf16
#pragma unroll
        for (int i = 0; i < 4; i++) {
            int lin = i * 256 + tid;
            int r = lin >> 3, c8 = (lin & 7) * 8;
            size_t g = (size_t)(brow + r) * 512 + k0 + c8;
            *(uint4*)(smem + S_AH + r * RSTRIDE + c8 * 2) = *(const uint4*)(Ah + g);
            *(uint4*)(smem + S_AL + r * RSTRIDE + c8 * 2) = *(const uint4*)(Al + g);
        }
        // stage W hi/lo: 256 n-rows x 64 bf16
#pragma unroll
        for (int i = 0; i < 8; i++) {
            int lin = i * 256 + tid;
            int n = lin >> 3, c8 = (lin & 7) * 8;
            size_t g = (size_t)n * 512 + k0 + c8;
            *(uint4*)(smem + S_WH + n * RSTRIDE + c8 * 2) = *(const uint4*)(Wh + g);
            *(uint4*)(smem + S_WL + n * RSTRIDE + c8 * 2) = *(const uint4*)(Wl + g);
        }
        __syncthreads();

#pragma unroll
        for (int ks = 0; ks < 4; ks++) {
            uint32_t ah[4][4], al[4][4];
#pragma unroll
            for (int mt = 0; mt < 4; mt++) {
                uint32_t addr = aBase + mt * (16 * RSTRIDE) + ks * 32;
                LDSM(ah[mt], addr);
                LDSM(al[mt], addr + (S_AL - S_AH));
            }
#pragma unroll
            for (int np = 0; np < 4; np++) {
                uint32_t bh[4], bl[4];
                uint32_t addr = bBase + np * (16 * RSTRIDE) + ks * 32;
                LDSM(bh, addr);
                LDSM(bl, addr + (S_WL - S_WH));
#pragma unroll
                for (int mt = 0; mt < 4; mt++) {
                    MMA(acc[mt][2 * np],     ah[mt], bh[0], bh[1]);
                    MMA(acc[mt][2 * np],     al[mt], bh[0], bh[1]);
                    MMA(acc[mt][2 * np],     ah[mt], bl[0], bl[1]);
                    MMA(acc[mt][2 * np + 1], ah[mt], bh[2], bh[3]);
                    MMA(acc[mt][2 * np + 1], al[mt], bh[2], bh[3]);
                    MMA(acc[mt][2 * np + 1], ah[mt], bl[2], bl[3]);
                }
            }
        }
    }

    // epilogue: bias + relu + cnt-mask, direct STG.64
#pragma unroll
    for (int mt = 0; mt < 4; mt++) {
        int r1 = brow + wm * 64 + mt * 16 + (lane >> 2);
        int r2 = r1 + 8;
        float k1 = (cnt[r1] > 0.f) ? 1.f : 0.f;
        float k2 = (cnt[r2] > 0.f) ? 1.f : 0.f;
#pragma unroll
        for (int nt = 0; nt < 8; nt++) {
            int c = wn * 64 + nt * 8 + (lane & 3) * 2;
            float bx = bias[c], by = bias[c + 1];
            float2 v1, v2;
            v1.x = fmaxf(acc[mt][nt][0] + bx, 0.f) * k1;
            v1.y = fmaxf(acc[mt][nt][1] + by, 0.f) * k1;
            v2.x = fmaxf(acc[mt][nt][2] + bx, 0.f) * k2;
            v2.y = fmaxf(acc[mt][nt][3] + by, 0.f) * k2;
            *(float2*)(C + (size_t)r1 * D + c) = v1;
            *(float2*)(C + (size_t)r2 * D + c) = v2;
        }
    }
}

// ---------------------------------------------------------------------------
// fp32 SGEMM for the small head GEMMs (proven)
// ---------------------------------------------------------------------------
template <int RELU>
__global__ void sgemm_k(const float* __restrict__ A, int lda,
                        const float* __restrict__ B, int N, int K,
                        const float* __restrict__ bias,
                        float* __restrict__ C, int ldc) {
    __shared__ float As[8][128];
    __shared__ float Bs[8][128];
    int tid = threadIdx.x;
    int brow = blockIdx.y * 128;
    int bcol = blockIdx.x * 128;
    int a_r = tid >> 1, a_c = (tid & 1) * 4;
    int b_r = tid >> 5, b_c = (tid & 31) * 4;
    int ty = tid >> 4, tx = tid & 15;
    float acc[8][8] = {};
    const float* Aptr = A + (size_t)(brow + a_r) * lda + a_c;
    const float* Bptr = B + (size_t)b_r * N + bcol + b_c;
    for (int k0 = 0; k0 < K; k0 += 8) {
        float4 av = *(const float4*)(Aptr + k0);
        float4 bv = *(const float4*)(Bptr + (size_t)k0 * N);
        As[a_c + 0][a_r] = av.x; As[a_c + 1][a_r] = av.y;
        As[a_c + 2][a_r] = av.z; As[a_c + 3][a_r] = av.w;
        *(float4*)&Bs[b_r][b_c] = bv;
        __syncthreads();
#pragma unroll
        for (int k = 0; k < 8; k++) {
            float ar[8], br[8];
            *(float4*)(ar) = *(const float4*)&As[k][ty * 8];
            *(float4*)(ar + 4) = *(const float4*)&As[k][ty * 8 + 4];
            *(float4*)(br) = *(const float4*)&Bs[k][tx * 8];
            *(float4*)(br + 4) = *(const float4*)&Bs[k][tx * 8 + 4];
#pragma unroll
            for (int i = 0; i < 8; i++)
#pragma unroll
                for (int j = 0; j < 8; j++) acc[i][j] += ar[i] * br[j];
        }
        __syncthreads();
    }
    float4 bv0 = *(const float4*)&bias[bcol + tx * 8];
    float4 bv1 = *(const float4*)&bias[bcol + tx * 8 + 4];
#pragma unroll
    for (int i = 0; i < 8; i++) {
        int r = brow + ty * 8 + i;
        float4 v0, v1;
        v0.x = acc[i][0] + bv0.x; v0.y = acc[i][1] + bv0.y;
        v0.z = acc[i][2] + bv0.z; v0.w = acc[i][3] + bv0.w;
        v1.x = acc[i][4] + bv1.x; v1.y = acc[i][5] + bv1.y;
        v1.z = acc[i][6] + bv1.z; v1.w = acc[i][7] + bv1.w;
        if (RELU) {
            v0.x = fmaxf(v0.x, 0.f); v0.y = fmaxf(v0.y, 0.f);
            v0.z = fmaxf(v0.z, 0.f); v0.w = fmaxf(v0.w, 0.f);
            v1.x = fmaxf(v1.x, 0.f); v1.y = fmaxf(v1.y, 0.f);
            v1.z = fmaxf(v1.z, 0.f); v1.w = fmaxf(v1.w, 0.f);
        }
        *(float4*)&C[(size_t)r * ldc + bcol + tx * 8] = v0;
        *(float4*)&C[(size_t)r * ldc + bcol + tx * 8 + 4] = v1;
    }
}

extern "C" void kernel_launch(void* const* d_in, const int* in_sizes, int n_in,
                              void* d_out, int out_size) {
    (void)in_sizes; (void)n_in; (void)out_size;
    const float* geometry = (const float*)d_in[0];
    const int*   semantic = (const int*)d_in[1];
    const int*   edge_index = (const int*)d_in[2];
    const float* W_geo = (const float*)d_in[4];
    const float* b_geo = (const float*)d_in[5];
    const float* emb   = (const float*)d_in[6];
    const float* W_lot = (const float*)d_in[7];
    const float* b_lot = (const float*)d_in[8];
    const float* W_mp[3] = {(const float*)d_in[9], (const float*)d_in[11], (const float*)d_in[13]};
    const float* b_mp[3] = {(const float*)d_in[10], (const float*)d_in[12], (const float*)d_in[14]};
    const float* W_agg = (const float*)d_in[15];
    const float* b_agg = (const float*)d_in[16];
    const float* W_mu  = (const float*)d_in[17];
    const float* b_mu  = (const float*)d_in[18];
    const float* W_var = (const float*)d_in[19];
    const float* b_var = (const float*)d_in[20];
    float* out = (float*)d_out;

    float *h, *cnt, *gvec, *latent;
    __nv_bfloat16 *Ahp, *Alp, *Wth, *Wtl;
    cudaGetSymbolAddress((void**)&h, g_h);
    cudaGetSymbolAddress((void**)&Ahp, g_Ah);
    cudaGetSymbolAddress((void**)&Alp, g_Al);
    cudaGetSymbolAddress((void**)&cnt, g_cnt);
    cudaGetSymbolAddress((void**)&gvec, g_gvec);
    cudaGetSymbolAddress((void**)&latent, g_latent);
    cudaGetSymbolAddress((void**)&Wth, g_Wth);
    cudaGetSymbolAddress((void**)&Wtl, g_Wtl);

    cudaFuncSetAttribute(mma_gemm_k, cudaFuncAttributeMaxDynamicSharedMemorySize, S_TOTAL);

    const int* esrc = edge_index;
    const int* edst = edge_index + NEDGES;

    precompute_k<<<17, 256>>>(W_geo, b_geo, emb, W_lot, b_lot);
    wsplit_k<<<1536, 256>>>(W_mp[0], W_mp[1], W_mp[2]);
    node_init_k<<<NNODES, 256>>>(geometry, semantic, W_lot);

    for (int r = 0; r < 3; r++) {
        gather_seg_k<<<BGR, 256>>>(h, Ahp, Alp, esrc, edst, r);
        mma_gemm_k<<<NNODES / 128, 256, S_TOTAL>>>(
            Ahp, Alp, Wth + (size_t)r * 131072, Wtl + (size_t)r * 131072,
            b_mp[r], cnt, h);
    }
    segmax_k<<<BGR, 256>>>(h, 3);

    sgemm_k<0><<<dim3(2, BGR / 128), 256>>>(gvec, 1024, W_agg, 256, 1024, b_agg, latent, 256);
    sgemm_k<0><<<dim3(2, BGR / 128), 256>>>(latent, 256, W_mu, 256, 256, b_mu, out, 256);
    sgemm_k<0><<<dim3(2, BGR / 128), 256>>>(latent, 256, W_var, 256, 256, b_var, out + (size_t)BGR * D, 256);
}

// round 7
// speedup vs baseline: 2.1144x; 1.1053x over previous
#include <cuda_runtime.h>
#include <cuda_bf16.h>
#include <cstdint>
#include <cstddef>

#define D 256
#define NB 30
#define BGR 2048
#define NNODES (BGR * NB)      // 61440
#define EPG 240
#define NEDGES (BGR * EPG)     // 491520

// ---------------- device scratch (allocation-free rule) ----------------
__device__ float g_h[(size_t)NNODES * D];        // current node features fp32
__device__ __nv_bfloat16 g_Ah[(size_t)NNODES * 512];  // split-bf16 GEMM A operand
__device__ __nv_bfloat16 g_Al[(size_t)NNODES * 512];
__device__ float g_cnt[NNODES];
__device__ float g_gvec[(size_t)BGR * 1024];     // [g0|g1|g2|g3]
__device__ float g_latent[(size_t)BGR * D];
__device__ float g_Wg[5 * D];
__device__ float g_emb2[11 * D];
__device__ float g_biasT[D];
// split-bf16 transposed msgpass weights: [3][N=256][K=512]
__device__ __nv_bfloat16 g_Wth[3 * 256 * 512];
__device__ __nv_bfloat16 g_Wtl[3 * 256 * 512];

// ---------------- helpers ----------------
__device__ __forceinline__ uint32_t smem_u32(const void* p) {
    uint32_t a;
    asm("{ .reg .u64 t; cvta.to.shared.u64 t, %1; cvt.u32.u64 %0, t; }" : "=r"(a) : "l"(p));
    return a;
}

#define LDSM(r, addr) \
    asm volatile("ldmatrix.sync.aligned.m8n8.x4.shared.b16 {%0,%1,%2,%3}, [%4];" \
        : "=r"((r)[0]), "=r"((r)[1]), "=r"((r)[2]), "=r"((r)[3]) : "r"(addr))

#define MMA(d, a, b0_, b1_) \
    asm volatile("mma.sync.aligned.m16n8k16.row.col.f32.bf16.bf16.f32 " \
        "{%0,%1,%2,%3}, {%4,%5,%6,%7}, {%8,%9}, {%0,%1,%2,%3};" \
        : "+f"((d)[0]), "+f"((d)[1]), "+f"((d)[2]), "+f"((d)[3]) \
        : "r"((a)[0]), "r"((a)[1]), "r"((a)[2]), "r"((a)[3]), "r"(b0_), "r"(b1_))

#define CP16(dst, src) \
    asm volatile("cp.async.cg.shared.global [%0], [%1], 16;" :: "r"(dst), "l"(src))
#define CP_COMMIT() asm volatile("cp.async.commit_group;")
#define CP_WAIT1()  asm volatile("cp.async.wait_group 1;")
#define CP_WAIT0()  asm volatile("cp.async.wait_group 0;")

// ---------------------------------------------------------------------------
// Fold input MLP weights
// ---------------------------------------------------------------------------
__global__ void precompute_k(const float* __restrict__ Wgeo,
                             const float* __restrict__ bgeo,
                             const float* __restrict__ emb,
                             const float* __restrict__ Wlot,
                             const float* __restrict__ blot) {
    int row = blockIdx.x;
    int c = threadIdx.x;
    float acc = 0.f;
    if (row < 5) {
        for (int j = 0; j < D; j++) acc += Wgeo[row * D + j] * Wlot[j * D + c];
        g_Wg[row * D + c] = acc;
    } else if (row < 16) {
        int s = row - 5;
        for (int j = 0; j < D; j++) acc += emb[s * D + j] * Wlot[(256 + j) * D + c];
        g_emb2[s * D + c] = acc;
    } else {
        for (int j = 0; j < D; j++) acc += bgeo[j] * Wlot[j * D + c];
        g_biasT[c] = acc + blot[c];
    }
}

// ---------------------------------------------------------------------------
// Split + transpose msgpass weights via smem tile (coalesced both sides):
// Wt[n][k] = W[k][n] as bf16 hi/lo.  Grid (8 n-tiles, 16 k-tiles, 3), block 32x8.
// ---------------------------------------------------------------------------
__global__ void wsplit_k(const float* __restrict__ W0,
                         const float* __restrict__ W1,
                         const float* __restrict__ W2) {
    __shared__ float sm[32][33];
    int m = blockIdx.z;
    const float* W = (m == 0) ? W0 : (m == 1) ? W1 : W2;
    int n0 = blockIdx.x * 32, k0 = blockIdx.y * 32;
    int tx = threadIdx.x, ty = threadIdx.y;
#pragma unroll
    for (int i = 0; i < 4; i++) {
        int k = k0 + ty + i * 8;
        sm[ty + i * 8][tx] = W[(size_t)k * 256 + n0 + tx];   // coalesced in n
    }
    __syncthreads();
#pragma unroll
    for (int i = 0; i < 4; i++) {
        int n = n0 + ty + i * 8;
        float v = sm[tx][ty + i * 8];
        __nv_bfloat16 hi = __float2bfloat16(v);
        __nv_bfloat16 lo = __float2bfloat16(v - __bfloat162float(hi));
        size_t o = (size_t)m * 131072 + (size_t)n * 512 + k0 + tx;  // coalesced in k
        g_Wth[o] = hi;
        g_Wtl[o] = lo;
    }
}

// ---------------------------------------------------------------------------
// h0 = relu(geometry@Wg + emb2[sem] + Wpos[pos] + biasT)
// ---------------------------------------------------------------------------
__global__ void node_init_k(const float* __restrict__ geom,
                            const int* __restrict__ sem,
                            const float* __restrict__ Wlot) {
    int node = blockIdx.x;
    int c = threadIdx.x;
    int pos = node % NB;
    int s = sem[node];
    float acc = g_biasT[c] + g_emb2[s * D + c] + Wlot[(512 + pos) * D + c];
#pragma unroll
    for (int k = 0; k < 5; k++) acc += geom[node * 5 + k] * g_Wg[k * D + c];
    g_h[(size_t)node * D + c] = fmaxf(acc, 0.f);
}

// ---------------------------------------------------------------------------
// Standalone segmax (final phase)
// ---------------------------------------------------------------------------
__global__ void segmax_k(const float* __restrict__ h, int phase) {
    int b = blockIdx.x;
    int c = threadIdx.x;
    const float* p = h + (size_t)b * NB * D + c;
    float m = -1e30f;
#pragma unroll
    for (int r = 0; r < NB; r++) m = fmaxf(m, p[(size_t)r * D]);
    g_gvec[(size_t)b * 1024 + phase * D + c] = m;
}

// ---------------------------------------------------------------------------
// Fused gather + segmax + split-bf16 operand production.
// ---------------------------------------------------------------------------
__global__ void gather_seg_k(const float* __restrict__ h,
                             __nv_bfloat16* __restrict__ Ah,
                             __nv_bfloat16* __restrict__ Al,
                             const int* __restrict__ esrc,
                             const int* __restrict__ edst,
                             int phase) {
    __shared__ float hb[NB * D];     // 30 KB
    __shared__ float cnt_s[NB], inv_s[NB];
    __shared__ int start_s[NB + 1], pos_s[NB];
    __shared__ int srt[EPG], ed_s[EPG], ed_d[EPG];
    int b = blockIdx.x, t = threadIdx.x;

    const float* base = h + (size_t)b * NB * D + t;
    float m = -1e30f;
#pragma unroll
    for (int r = 0; r < NB; r++) {
        float v = base[(size_t)r * D];
        hb[r * D + t] = v;
        m = fmaxf(m, v);
        __nv_bfloat16 hi = __float2bfloat16(v);
        __nv_bfloat16 lo = __float2bfloat16(v - __bfloat162float(hi));
        size_t row = (size_t)(b * NB + r) * 512;
        Ah[row + t] = hi;
        Al[row + t] = lo;
    }
    g_gvec[(size_t)b * 1024 + phase * D + t] = m;
    if (t < NB) cnt_s[t] = 0.f;
    __syncthreads();
    if (t < EPG) {
        int s = esrc[(size_t)b * EPG + t] - b * NB;
        int d0 = edst[(size_t)b * EPG + t] - b * NB;
        ed_s[t] = s;
        ed_d[t] = d0;
        atomicAdd(&cnt_s[d0], 1.f);
    }
    __syncthreads();
    if (t == 0) {
        int acc = 0;
        for (int r = 0; r < NB; r++) {
            start_s[r] = acc;
            pos_s[r] = acc;
            acc += (int)cnt_s[r];
        }
        start_s[NB] = acc;
    }
    __syncthreads();
    if (t < EPG) {
        int idx = atomicAdd(&pos_s[ed_d[t]], 1);
        srt[idx] = ed_s[t];
    }
    if (t < NB) {
        float c = cnt_s[t];
        inv_s[t] = (c > 0.f) ? 1.f / c : 0.f;
        g_cnt[b * NB + t] = c;
    }
    __syncthreads();

    for (int r = 0; r < NB; r++) {
        float acc = 0.f;
        int e0 = start_s[r], e1 = start_s[r + 1];
        for (int j = e0; j < e1; j++) acc += hb[srt[j] * D + t];
        float v = acc * inv_s[r];
        __nv_bfloat16 hi = __float2bfloat16(v);
        __nv_bfloat16 lo = __float2bfloat16(v - __bfloat162float(hi));
        size_t row = (size_t)(b * NB + r) * 512;
        Ah[row + 256 + t] = hi;
        Al[row + 256 + t] = lo;
    }
}

// ---------------------------------------------------------------------------
// Split-bf16 tensor-core GEMM via mma.sync + cp.async double buffering:
//   C[61440,256] = mask * relu(A[61440,512] @ Wt^T + bias)
// CTA: 128 M x 128 N (grid 2 x 480), 8 warps of 64x32, K chunked by 64.
// 3 mma products: Ah*Wh + Al*Wh + Ah*Wl.
// ---------------------------------------------------------------------------
#define KC 64
#define RSTRIDE 144                  // 128B row + 16B pad
#define OFF_AH 0
#define OFF_AL 18432
#define OFF_WH 36864
#define OFF_WL 55296
#define S_STAGE 73728
#define S_TOTAL (2 * S_STAGE)        // 147456

__device__ __forceinline__ void stage_load(uint32_t base,
                                           const __nv_bfloat16* __restrict__ Ah,
                                           const __nv_bfloat16* __restrict__ Al,
                                           const __nv_bfloat16* __restrict__ Wh,
                                           const __nv_bfloat16* __restrict__ Wl,
                                           int brow, int k0, int tid) {
#pragma unroll
    for (int i = 0; i < 4; i++) {
        int lin = i * 256 + tid;
        int r = lin >> 3, c8 = (lin & 7) * 8;
        uint32_t doff = (uint32_t)(r * RSTRIDE + c8 * 2);
        size_t ga = (size_t)(brow + r) * 512 + k0 + c8;
        size_t gw = (size_t)r * 512 + k0 + c8;
        CP16(base + OFF_AH + doff, Ah + ga);
        CP16(base + OFF_AL + doff, Al + ga);
        CP16(base + OFF_WH + doff, Wh + gw);
        CP16(base + OFF_WL + doff, Wl + gw);
    }
}

__global__ void __launch_bounds__(256, 1)
mma_gemm_k(const __nv_bfloat16* __restrict__ Ah,
           const __nv_bfloat16* __restrict__ Al,
           const __nv_bfloat16* __restrict__ WhBase,
           const __nv_bfloat16* __restrict__ WlBase,
           const float* __restrict__ bias,
           const float* __restrict__ cnt,
           float* __restrict__ C) {
    extern __shared__ char smem[];
    uint32_t sb = smem_u32(smem);
    int tid = threadIdx.x;
    int lane = tid & 31, wid = tid >> 5;
    int brow = blockIdx.y * 128;
    int noff = blockIdx.x * 128;
    const __nv_bfloat16* Wh = WhBase + (size_t)noff * 512;
    const __nv_bfloat16* Wl = WlBase + (size_t)noff * 512;
    int wm = wid & 1;          // M warp (2) -> 64 rows
    int wn = wid >> 1;         // N warp (4) -> 32 cols

    float acc[4][4][4];
#pragma unroll
    for (int i = 0; i < 4; i++)
#pragma unroll
        for (int j = 0; j < 4; j++)
#pragma unroll
            for (int q = 0; q < 4; q++) acc[i][j][q] = 0.f;

    uint32_t aOff = (uint32_t)((wm * 64 + (lane & 15)) * RSTRIDE + (lane >> 4) * 16);
    int bq = lane >> 3;
    uint32_t bOff = (uint32_t)((wn * 32 + (lane & 7) + (bq & 2) * 4) * RSTRIDE + (bq & 1) * 16);

    // preload chunk 0
    stage_load(sb, Ah, Al, Wh, Wl, brow, 0, tid);
    CP_COMMIT();

    for (int c = 0; c < 8; c++) {
        uint32_t cur = sb + (uint32_t)(c & 1) * S_STAGE;
        if (c < 7) {
            stage_load(sb + (uint32_t)((c + 1) & 1) * S_STAGE, Ah, Al, Wh, Wl,
                       brow, (c + 1) * KC, tid);
            CP_COMMIT();
            CP_WAIT1();
        } else {
            CP_WAIT0();
        }
        __syncthreads();

        uint32_t aBase = cur + aOff;
        uint32_t bBase = cur + bOff;
#pragma unroll
        for (int ks = 0; ks < 4; ks++) {
            uint32_t ah[4][4], al[4][4];
#pragma unroll
            for (int mt = 0; mt < 4; mt++) {
                uint32_t addr = aBase + mt * (16 * RSTRIDE) + ks * 32;
                LDSM(ah[mt], addr + OFF_AH);
                LDSM(al[mt], addr + OFF_AL);
            }
#pragma unroll
            for (int np = 0; np < 2; np++) {
                uint32_t bh[4], bl[4];
                uint32_t addr = bBase + np * (16 * RSTRIDE) + ks * 32;
                LDSM(bh, addr + OFF_WH);
                LDSM(bl, addr + OFF_WL);
#pragma unroll
                for (int mt = 0; mt < 4; mt++) {
                    MMA(acc[mt][2 * np],     ah[mt], bh[0], bh[1]);
                    MMA(acc[mt][2 * np],     al[mt], bh[0], bh[1]);
                    MMA(acc[mt][2 * np],     ah[mt], bl[0], bl[1]);
                    MMA(acc[mt][2 * np + 1], ah[mt], bh[2], bh[3]);
                    MMA(acc[mt][2 * np + 1], al[mt], bh[2], bh[3]);
                    MMA(acc[mt][2 * np + 1], ah[mt], bl[2], bl[3]);
                }
            }
        }
        __syncthreads();
    }

    // epilogue: bias + relu + cnt-mask, direct STG.64
#pragma unroll
    for (int mt = 0; mt < 4; mt++) {
        int r1 = brow + wm * 64 + mt * 16 + (lane >> 2);
        int r2 = r1 + 8;
        float k1 = (cnt[r1] > 0.f) ? 1.f : 0.f;
        float k2 = (cnt[r2] > 0.f) ? 1.f : 0.f;
#pragma unroll
        for (int nt = 0; nt < 4; nt++) {
            int cc = noff + wn * 32 + nt * 8 + (lane & 3) * 2;
            float bx = bias[cc], by = bias[cc + 1];
            float2 v1, v2;
            v1.x = fmaxf(acc[mt][nt][0] + bx, 0.f) * k1;
            v1.y = fmaxf(acc[mt][nt][1] + by, 0.f) * k1;
            v2.x = fmaxf(acc[mt][nt][2] + bx, 0.f) * k2;
            v2.y = fmaxf(acc[mt][nt][3] + by, 0.f) * k2;
            *(float2*)(C + (size_t)r1 * D + cc) = v1;
            *(float2*)(C + (size_t)r2 * D + cc) = v2;
        }
    }
}

// ---------------------------------------------------------------------------
// fp32 SGEMM for the small head GEMMs (proven)
// ---------------------------------------------------------------------------
template <int RELU>
__global__ void sgemm_k(const float* __restrict__ A, int lda,
                        const float* __restrict__ B, int N, int K,
                        const float* __restrict__ bias,
                        float* __restrict__ C, int ldc) {
    __shared__ float As[8][128];
    __shared__ float Bs[8][128];
    int tid = threadIdx.x;
    int brow = blockIdx.y * 128;
    int bcol = blockIdx.x * 128;
    int a_r = tid >> 1, a_c = (tid & 1) * 4;
    int b_r = tid >> 5, b_c = (tid & 31) * 4;
    int ty = tid >> 4, tx = tid & 15;
    float acc[8][8] = {};
    const float* Aptr = A + (size_t)(brow + a_r) * lda + a_c;
    const float* Bptr = B + (size_t)b_r * N + bcol + b_c;
    for (int k0 = 0; k0 < K; k0 += 8) {
        float4 av = *(const float4*)(Aptr + k0);
        float4 bv = *(const float4*)(Bptr + (size_t)k0 * N);
        As[a_c + 0][a_r] = av.x; As[a_c + 1][a_r] = av.y;
        As[a_c + 2][a_r] = av.z; As[a_c + 3][a_r] = av.w;
        *(float4*)&Bs[b_r][b_c] = bv;
        __syncthreads();
#pragma unroll
        for (int k = 0; k < 8; k++) {
            float ar[8], br[8];
            *(float4*)(ar) = *(const float4*)&As[k][ty * 8];
            *(float4*)(ar + 4) = *(const float4*)&As[k][ty * 8 + 4];
            *(float4*)(br) = *(const float4*)&Bs[k][tx * 8];
            *(float4*)(br + 4) = *(const float4*)&Bs[k][tx * 8 + 4];
#pragma unroll
            for (int i = 0; i < 8; i++)
#pragma unroll
                for (int j = 0; j < 8; j++) acc[i][j] += ar[i] * br[j];
        }
        __syncthreads();
    }
    float4 bv0 = *(const float4*)&bias[bcol + tx * 8];
    float4 bv1 = *(const float4*)&bias[bcol + tx * 8 + 4];
#pragma unroll
    for (int i = 0; i < 8; i++) {
        int r = brow + ty * 8 + i;
        float4 v0, v1;
        v0.x = acc[i][0] + bv0.x; v0.y = acc[i][1] + bv0.y;
        v0.z = acc[i][2] + bv0.z; v0.w = acc[i][3] + bv0.w;
        v1.x = acc[i][4] + bv1.x; v1.y = acc[i][5] + bv1.y;
        v1.z = acc[i][6] + bv1.z; v1.w = acc[i][7] + bv1.w;
        if (RELU) {
            v0.x = fmaxf(v0.x, 0.f); v0.y = fmaxf(v0.y, 0.f);
            v0.z = fmaxf(v0.z, 0.f); v0.w = fmaxf(v0.w, 0.f);
            v1.x = fmaxf(v1.x, 0.f); v1.y = fmaxf(v1.y, 0.f);
            v1.w = fmaxf(v1.w, 0.f); v1.z = fmaxf(v1.z, 0.f);
        }
        *(float4*)&C[(size_t)r * ldc + bcol + tx * 8] = v0;
        *(float4*)&C[(size_t)r * ldc + bcol + tx * 8 + 4] = v1;
    }
}

extern "C" void kernel_launch(void* const* d_in, const int* in_sizes, int n_in,
                              void* d_out, int out_size) {
    (void)in_sizes; (void)n_in; (void)out_size;
    const float* geometry = (const float*)d_in[0];
    const int*   semantic = (const int*)d_in[1];
    const int*   edge_index = (const int*)d_in[2];
    const float* W_geo = (const float*)d_in[4];
    const float* b_geo = (const float*)d_in[5];
    const float* emb   = (const float*)d_in[6];
    const float* W_lot = (const float*)d_in[7];
    const float* b_lot = (const float*)d_in[8];
    const float* W_mp[3] = {(const float*)d_in[9], (const float*)d_in[11], (const float*)d_in[13]};
    const float* b_mp[3] = {(const float*)d_in[10], (const float*)d_in[12], (const float*)d_in[14]};
    const float* W_agg = (const float*)d_in[15];
    const float* b_agg = (const float*)d_in[16];
    const float* W_mu  = (const float*)d_in[17];
    const float* b_mu  = (const float*)d_in[18];
    const float* W_var = (const float*)d_in[19];
    const float* b_var = (const float*)d_in[20];
    float* out = (float*)d_out;

    float *h, *cnt, *gvec, *latent;
    __nv_bfloat16 *Ahp, *Alp, *Wth, *Wtl;
    cudaGetSymbolAddress((void**)&h, g_h);
    cudaGetSymbolAddress((void**)&Ahp, g_Ah);
    cudaGetSymbolAddress((void**)&Alp, g_Al);
    cudaGetSymbolAddress((void**)&cnt, g_cnt);
    cudaGetSymbolAddress((void**)&gvec, g_gvec);
    cudaGetSymbolAddress((void**)&latent, g_latent);
    cudaGetSymbolAddress((void**)&Wth, g_Wth);
    cudaGetSymbolAddress((void**)&Wtl, g_Wtl);

    cudaFuncSetAttribute(mma_gemm_k, cudaFuncAttributeMaxDynamicSharedMemorySize, S_TOTAL);

    const int* esrc = edge_index;
    const int* edst = edge_index + NEDGES;

    precompute_k<<<17, 256>>>(W_geo, b_geo, emb, W_lot, b_lot);
    wsplit_k<<<dim3(8, 16, 3), dim3(32, 8)>>>(W_mp[0], W_mp[1], W_mp[2]);
    node_init_k<<<NNODES, 256>>>(geometry, semantic, W_lot);

    for (int r = 0; r < 3; r++) {
        gather_seg_k<<<BGR, 256>>>(h, Ahp, Alp, esrc, edst, r);
        mma_gemm_k<<<dim3(2, NNODES / 128), 256, S_TOTAL>>>(
            Ahp, Alp, Wth + (size_t)r * 131072, Wtl + (size_t)r * 131072,
            b_mp[r], cnt, h);
    }
    segmax_k<<<BGR, 256>>>(h, 3);

    sgemm_k<0><<<dim3(2, BGR / 128), 256>>>(gvec, 1024, W_agg, 256, 1024, b_agg, latent, 256);
    sgemm_k<0><<<dim3(2, BGR / 128), 256>>>(latent, 256, W_mu, 256, 256, b_mu, out, 256);
    sgemm_k<0><<<dim3(2, BGR / 128), 256>>>(latent, 256, W_var, 256, 256, b_var, out + (size_t)BGR * D, 256);
}

// round 8
// speedup vs baseline: 2.2654x; 1.0714x over previous
#include <cuda_runtime.h>
#include <cuda_bf16.h>
#include <cstdint>
#include <cstddef>

#define D 256
#define NB 30
#define BGR 2048
#define NNODES (BGR * NB)      // 61440
#define EPG 240
#define NEDGES (BGR * EPG)     // 491520

// ---------------- device scratch (allocation-free rule) ----------------
__device__ float g_h[(size_t)NNODES * D];        // current node features fp32
__device__ __nv_bfloat16 g_Ah[(size_t)NNODES * 512];  // split-bf16 GEMM A operand
__device__ __nv_bfloat16 g_Al[(size_t)NNODES * 512];
__device__ float g_cnt[NNODES];
__device__ float g_gvec[(size_t)BGR * 1024];     // [g0|g1|g2|g3]
__device__ float g_latent[(size_t)BGR * D];
__device__ float g_Wg[5 * D];
__device__ float g_emb2[11 * D];
__device__ float g_biasT[D];
// split-bf16 transposed msgpass weights: [3][N=256][K=512]
__device__ __nv_bfloat16 g_Wth[3 * 256 * 512];
__device__ __nv_bfloat16 g_Wtl[3 * 256 * 512];

// ---------------- helpers ----------------
__device__ __forceinline__ uint32_t smem_u32(const void* p) {
    uint32_t a;
    asm("{ .reg .u64 t; cvta.to.shared.u64 t, %1; cvt.u32.u64 %0, t; }" : "=r"(a) : "l"(p));
    return a;
}

#define LDSM(r, addr) \
    asm volatile("ldmatrix.sync.aligned.m8n8.x4.shared.b16 {%0,%1,%2,%3}, [%4];" \
        : "=r"((r)[0]), "=r"((r)[1]), "=r"((r)[2]), "=r"((r)[3]) : "r"(addr))

#define MMA(d, a, b0_, b1_) \
    asm volatile("mma.sync.aligned.m16n8k16.row.col.f32.bf16.bf16.f32 " \
        "{%0,%1,%2,%3}, {%4,%5,%6,%7}, {%8,%9}, {%0,%1,%2,%3};" \
        : "+f"((d)[0]), "+f"((d)[1]), "+f"((d)[2]), "+f"((d)[3]) \
        : "r"((a)[0]), "r"((a)[1]), "r"((a)[2]), "r"((a)[3]), "r"(b0_), "r"(b1_))

#define CP16(dst, src) \
    asm volatile("cp.async.cg.shared.global [%0], [%1], 16;" :: "r"(dst), "l"(src))
#define CP_COMMIT() asm volatile("cp.async.commit_group;")
#define CP_WAIT1()  asm volatile("cp.async.wait_group 1;")
#define CP_WAIT0()  asm volatile("cp.async.wait_group 0;")

// ---------------------------------------------------------------------------
// Fold input MLP weights
// ---------------------------------------------------------------------------
__global__ void precompute_k(const float* __restrict__ Wgeo,
                             const float* __restrict__ bgeo,
                             const float* __restrict__ emb,
                             const float* __restrict__ Wlot,
                             const float* __restrict__ blot) {
    int row = blockIdx.x;
    int c = threadIdx.x;
    float acc = 0.f;
    if (row < 5) {
        for (int j = 0; j < D; j++) acc += Wgeo[row * D + j] * Wlot[j * D + c];
        g_Wg[row * D + c] = acc;
    } else if (row < 16) {
        int s = row - 5;
        for (int j = 0; j < D; j++) acc += emb[s * D + j] * Wlot[(256 + j) * D + c];
        g_emb2[s * D + c] = acc;
    } else {
        for (int j = 0; j < D; j++) acc += bgeo[j] * Wlot[j * D + c];
        g_biasT[c] = acc + blot[c];
    }
}

// ---------------------------------------------------------------------------
// Split + transpose msgpass weights via smem tile (coalesced both sides)
// ---------------------------------------------------------------------------
__global__ void wsplit_k(const float* __restrict__ W0,
                         const float* __restrict__ W1,
                         const float* __restrict__ W2) {
    __shared__ float sm[32][33];
    int m = blockIdx.z;
    const float* W = (m == 0) ? W0 : (m == 1) ? W1 : W2;
    int n0 = blockIdx.x * 32, k0 = blockIdx.y * 32;
    int tx = threadIdx.x, ty = threadIdx.y;
#pragma unroll
    for (int i = 0; i < 4; i++) {
        int k = k0 + ty + i * 8;
        sm[ty + i * 8][tx] = W[(size_t)k * 256 + n0 + tx];
    }
    __syncthreads();
#pragma unroll
    for (int i = 0; i < 4; i++) {
        int n = n0 + ty + i * 8;
        float v = sm[tx][ty + i * 8];
        __nv_bfloat16 hi = __float2bfloat16(v);
        __nv_bfloat16 lo = __float2bfloat16(v - __bfloat162float(hi));
        size_t o = (size_t)m * 131072 + (size_t)n * 512 + k0 + tx;
        g_Wth[o] = hi;
        g_Wtl[o] = lo;
    }
}

// ---------------------------------------------------------------------------
// h0 = relu(geometry@Wg + emb2[sem] + Wpos[pos] + biasT)
// ---------------------------------------------------------------------------
__global__ void node_init_k(const float* __restrict__ geom,
                            const int* __restrict__ sem,
                            const float* __restrict__ Wlot) {
    int node = blockIdx.x;
    int c = threadIdx.x;
    int pos = node % NB;
    int s = sem[node];
    float acc = g_biasT[c] + g_emb2[s * D + c] + Wlot[(512 + pos) * D + c];
#pragma unroll
    for (int k = 0; k < 5; k++) acc += geom[node * 5 + k] * g_Wg[k * D + c];
    g_h[(size_t)node * D + c] = fmaxf(acc, 0.f);
}

// ---------------------------------------------------------------------------
// Standalone segmax (final phase)
// ---------------------------------------------------------------------------
__global__ void segmax_k(const float* __restrict__ h, int phase) {
    int b = blockIdx.x;
    int c = threadIdx.x;
    const float* p = h + (size_t)b * NB * D + c;
    float m = -1e30f;
#pragma unroll
    for (int r = 0; r < NB; r++) m = fmaxf(m, p[(size_t)r * D]);
    g_gvec[(size_t)b * 1024 + phase * D + c] = m;
}

// ---------------------------------------------------------------------------
// Fused gather + segmax + split-bf16 operand production.
// ---------------------------------------------------------------------------
__global__ void gather_seg_k(const float* __restrict__ h,
                             __nv_bfloat16* __restrict__ Ah,
                             __nv_bfloat16* __restrict__ Al,
                             const int* __restrict__ esrc,
                             const int* __restrict__ edst,
                             int phase) {
    __shared__ float hb[NB * D];     // 30 KB
    __shared__ float cnt_s[NB], inv_s[NB];
    __shared__ int start_s[NB + 1], pos_s[NB];
    __shared__ int srt[EPG], ed_s[EPG], ed_d[EPG];
    int b = blockIdx.x, t = threadIdx.x;

    const float* base = h + (size_t)b * NB * D + t;
    float m = -1e30f;
#pragma unroll
    for (int r = 0; r < NB; r++) {
        float v = base[(size_t)r * D];
        hb[r * D + t] = v;
        m = fmaxf(m, v);
        __nv_bfloat16 hi = __float2bfloat16(v);
        __nv_bfloat16 lo = __float2bfloat16(v - __bfloat162float(hi));
        size_t row = (size_t)(b * NB + r) * 512;
        Ah[row + t] = hi;
        Al[row + t] = lo;
    }
    g_gvec[(size_t)b * 1024 + phase * D + t] = m;
    if (t < NB) cnt_s[t] = 0.f;
    __syncthreads();
    if (t < EPG) {
        int s = esrc[(size_t)b * EPG + t] - b * NB;
        int d0 = edst[(size_t)b * EPG + t] - b * NB;
        ed_s[t] = s;
        ed_d[t] = d0;
        atomicAdd(&cnt_s[d0], 1.f);
    }
    __syncthreads();
    if (t == 0) {
        int acc = 0;
        for (int r = 0; r < NB; r++) {
            start_s[r] = acc;
            pos_s[r] = acc;
            acc += (int)cnt_s[r];
        }
        start_s[NB] = acc;
    }
    __syncthreads();
    if (t < EPG) {
        int idx = atomicAdd(&pos_s[ed_d[t]], 1);
        srt[idx] = ed_s[t];
    }
    if (t < NB) {
        float c = cnt_s[t];
        inv_s[t] = (c > 0.f) ? 1.f / c : 0.f;
        g_cnt[b * NB + t] = c;
    }
    __syncthreads();

    for (int r = 0; r < NB; r++) {
        float acc = 0.f;
        int e0 = start_s[r], e1 = start_s[r + 1];
        for (int j = e0; j < e1; j++) acc += hb[srt[j] * D + t];
        float v = acc * inv_s[r];
        __nv_bfloat16 hi = __float2bfloat16(v);
        __nv_bfloat16 lo = __float2bfloat16(v - __bfloat162float(hi));
        size_t row = (size_t)(b * NB + r) * 512;
        Ah[row + 256 + t] = hi;
        Al[row + 256 + t] = lo;
    }
}

// ---------------------------------------------------------------------------
// Split-bf16 tensor-core GEMM via mma.sync + cp.async double buffering.
// CTA: 128 M x 128 N (grid 2 x 480), 8 warps of 64x32, K chunked by 32.
// Stage = 40KB, 2 stages = 80KB -> 2 CTAs/SM.
// 3 mma products: Ah*Wh + Al*Wh + Ah*Wl.
// ---------------------------------------------------------------------------
#define KC 32
#define RSTRIDE 80                   // 64B row + 16B pad (16B-aligned, conflict-free)
#define OFF_AH 0
#define OFF_AL 10240
#define OFF_WH 20480
#define OFF_WL 30720
#define S_STAGE 40960
#define S_TOTAL (2 * S_STAGE)        // 81920
#define NCHUNK 16

__device__ __forceinline__ void stage_load(uint32_t base,
                                           const __nv_bfloat16* __restrict__ Ah,
                                           const __nv_bfloat16* __restrict__ Al,
                                           const __nv_bfloat16* __restrict__ Wh,
                                           const __nv_bfloat16* __restrict__ Wl,
                                           int brow, int k0, int tid) {
#pragma unroll
    for (int i = 0; i < 2; i++) {
        int lin = i * 256 + tid;
        int r = lin >> 2, c8 = (lin & 3) * 8;
        uint32_t doff = (uint32_t)(r * RSTRIDE + c8 * 2);
        size_t ga = (size_t)(brow + r) * 512 + k0 + c8;
        size_t gw = (size_t)r * 512 + k0 + c8;
        CP16(base + OFF_AH + doff, Ah + ga);
        CP16(base + OFF_AL + doff, Al + ga);
        CP16(base + OFF_WH + doff, Wh + gw);
        CP16(base + OFF_WL + doff, Wl + gw);
    }
}

__global__ void __launch_bounds__(256, 2)
mma_gemm_k(const __nv_bfloat16* __restrict__ Ah,
           const __nv_bfloat16* __restrict__ Al,
           const __nv_bfloat16* __restrict__ WhBase,
           const __nv_bfloat16* __restrict__ WlBase,
           const float* __restrict__ bias,
           const float* __restrict__ cnt,
           float* __restrict__ C) {
    extern __shared__ char smem[];
    uint32_t sb = smem_u32(smem);
    int tid = threadIdx.x;
    int lane = tid & 31, wid = tid >> 5;
    int brow = blockIdx.y * 128;
    int noff = blockIdx.x * 128;
    const __nv_bfloat16* Wh = WhBase + (size_t)noff * 512;
    const __nv_bfloat16* Wl = WlBase + (size_t)noff * 512;
    int wm = wid & 1;          // M warp (2) -> 64 rows
    int wn = wid >> 1;         // N warp (4) -> 32 cols

    float acc[4][4][4];
#pragma unroll
    for (int i = 0; i < 4; i++)
#pragma unroll
        for (int j = 0; j < 4; j++)
#pragma unroll
            for (int q = 0; q < 4; q++) acc[i][j][q] = 0.f;

    uint32_t aOff = (uint32_t)((wm * 64 + (lane & 15)) * RSTRIDE + (lane >> 4) * 16);
    int bq = lane >> 3;
    uint32_t bOff = (uint32_t)((wn * 32 + (lane & 7) + (bq & 2) * 4) * RSTRIDE + (bq & 1) * 16);

    // preload chunk 0
    stage_load(sb, Ah, Al, Wh, Wl, brow, 0, tid);
    CP_COMMIT();

    for (int c = 0; c < NCHUNK; c++) {
        uint32_t cur = sb + (uint32_t)(c & 1) * S_STAGE;
        if (c < NCHUNK - 1) {
            stage_load(sb + (uint32_t)((c + 1) & 1) * S_STAGE, Ah, Al, Wh, Wl,
                       brow, (c + 1) * KC, tid);
            CP_COMMIT();
            CP_WAIT1();
        } else {
            CP_WAIT0();
        }
        __syncthreads();

        uint32_t aBase = cur + aOff;
        uint32_t bBase = cur + bOff;
#pragma unroll
        for (int ks = 0; ks < 2; ks++) {
            uint32_t ah[4][4], al[4][4];
#pragma unroll
            for (int mt = 0; mt < 4; mt++) {
                uint32_t addr = aBase + mt * (16 * RSTRIDE) + ks * 32;
                LDSM(ah[mt], addr + OFF_AH);
                LDSM(al[mt], addr + OFF_AL);
            }
#pragma unroll
            for (int np = 0; np < 2; np++) {
                uint32_t bh[4], bl[4];
                uint32_t addr = bBase + np * (16 * RSTRIDE) + ks * 32;
                LDSM(bh, addr + OFF_WH);
                LDSM(bl, addr + OFF_WL);
#pragma unroll
                for (int mt = 0; mt < 4; mt++) {
                    MMA(acc[mt][2 * np],     ah[mt], bh[0], bh[1]);
                    MMA(acc[mt][2 * np],     al[mt], bh[0], bh[1]);
                    MMA(acc[mt][2 * np],     ah[mt], bl[0], bl[1]);
                    MMA(acc[mt][2 * np + 1], ah[mt], bh[2], bh[3]);
                    MMA(acc[mt][2 * np + 1], al[mt], bh[2], bh[3]);
                    MMA(acc[mt][2 * np + 1], ah[mt], bl[2], bl[3]);
                }
            }
        }
        __syncthreads();
    }

    // epilogue: bias + relu + cnt-mask, direct STG.64
#pragma unroll
    for (int mt = 0; mt < 4; mt++) {
        int r1 = brow + wm * 64 + mt * 16 + (lane >> 2);
        int r2 = r1 + 8;
        float k1 = (cnt[r1] > 0.f) ? 1.f : 0.f;
        float k2 = (cnt[r2] > 0.f) ? 1.f : 0.f;
#pragma unroll
        for (int nt = 0; nt < 4; nt++) {
            int cc = noff + wn * 32 + nt * 8 + (lane & 3) * 2;
            float bx = bias[cc], by = bias[cc + 1];
            float2 v1, v2;
            v1.x = fmaxf(acc[mt][nt][0] + bx, 0.f) * k1;
            v1.y = fmaxf(acc[mt][nt][1] + by, 0.f) * k1;
            v2.x = fmaxf(acc[mt][nt][2] + bx, 0.f) * k2;
            v2.y = fmaxf(acc[mt][nt][3] + by, 0.f) * k2;
            *(float2*)(C + (size_t)r1 * D + cc) = v1;
            *(float2*)(C + (size_t)r2 * D + cc) = v2;
        }
    }
}

// ---------------------------------------------------------------------------
// fp32 SGEMM, 64x128 tile (more CTAs for the small head GEMMs)
// Grid: (N/128, M/64), 256 threads, each 4x8.
// ---------------------------------------------------------------------------
__global__ void sgemm64_k(const float* __restrict__ A, int lda,
                          const float* __restrict__ B, int N, int K,
                          const float* __restrict__ bias,
                          float* __restrict__ C, int ldc) {
    __shared__ float As[8][64];
    __shared__ float Bs[8][128];
    int tid = threadIdx.x;
    int brow = blockIdx.y * 64;
    int bcol = blockIdx.x * 128;
    int a_r = tid >> 2, a_c = (tid & 3) * 2;
    int b_r = tid >> 5, b_c = (tid & 31) * 4;
    int ty = tid >> 4, tx = tid & 15;
    float acc[4][8] = {};
    const float* Aptr = A + (size_t)(brow + a_r) * lda + a_c;
    const float* Bptr = B + (size_t)b_r * N + bcol + b_c;
    for (int k0 = 0; k0 < K; k0 += 8) {
        float2 av = *(const float2*)(Aptr + k0);
        float4 bv = *(const float4*)(Bptr + (size_t)k0 * N);
        As[a_c + 0][a_r] = av.x;
        As[a_c + 1][a_r] = av.y;
        *(float4*)&Bs[b_r][b_c] = bv;
        __syncthreads();
#pragma unroll
        for (int k = 0; k < 8; k++) {
            float ar[4], br[8];
            *(float4*)(ar) = *(const float4*)&As[k][ty * 4];
            *(float4*)(br) = *(const float4*)&Bs[k][tx * 8];
            *(float4*)(br + 4) = *(const float4*)&Bs[k][tx * 8 + 4];
#pragma unroll
            for (int i = 0; i < 4; i++)
#pragma unroll
                for (int j = 0; j < 8; j++) acc[i][j] += ar[i] * br[j];
        }
        __syncthreads();
    }
    float4 bv0 = *(const float4*)&bias[bcol + tx * 8];
    float4 bv1 = *(const float4*)&bias[bcol + tx * 8 + 4];
#pragma unroll
    for (int i = 0; i < 4; i++) {
        int r = brow + ty * 4 + i;
        float4 v0, v1;
        v0.x = acc[i][0] + bv0.x; v0.y = acc[i][1] + bv0.y;
        v0.z = acc[i][2] + bv0.z; v0.w = acc[i][3] + bv0.w;
        v1.x = acc[i][4] + bv1.x; v1.y = acc[i][5] + bv1.y;
        v1.z = acc[i][6] + bv1.z; v1.w = acc[i][7] + bv1.w;
        *(float4*)&C[(size_t)r * ldc + bcol + tx * 8] = v0;
        *(float4*)&C[(size_t)r * ldc + bcol + tx * 8 + 4] = v1;
    }
}

extern "C" void kernel_launch(void* const* d_in, const int* in_sizes, int n_in,
                              void* d_out, int out_size) {
    (void)in_sizes; (void)n_in; (void)out_size;
    const float* geometry = (const float*)d_in[0];
    const int*   semantic = (const int*)d_in[1];
    const int*   edge_index = (const int*)d_in[2];
    const float* W_geo = (const float*)d_in[4];
    const float* b_geo = (const float*)d_in[5];
    const float* emb   = (const float*)d_in[6];
    const float* W_lot = (const float*)d_in[7];
    const float* b_lot = (const float*)d_in[8];
    const float* W_mp[3] = {(const float*)d_in[9], (const float*)d_in[11], (const float*)d_in[13]};
    const float* b_mp[3] = {(const float*)d_in[10], (const float*)d_in[12], (const float*)d_in[14]};
    const float* W_agg = (const float*)d_in[15];
    const float* b_agg = (const float*)d_in[16];
    const float* W_mu  = (const float*)d_in[17];
    const float* b_mu  = (const float*)d_in[18];
    const float* W_var = (const float*)d_in[19];
    const float* b_var = (const float*)d_in[20];
    float* out = (float*)d_out;

    float *h, *cnt, *gvec, *latent;
    __nv_bfloat16 *Ahp, *Alp, *Wth, *Wtl;
    cudaGetSymbolAddress((void**)&h, g_h);
    cudaGetSymbolAddress((void**)&Ahp, g_Ah);
    cudaGetSymbolAddress((void**)&Alp, g_Al);
    cudaGetSymbolAddress((void**)&cnt, g_cnt);
    cudaGetSymbolAddress((void**)&gvec, g_gvec);
    cudaGetSymbolAddress((void**)&latent, g_latent);
    cudaGetSymbolAddress((void**)&Wth, g_Wth);
    cudaGetSymbolAddress((void**)&Wtl, g_Wtl);

    cudaFuncSetAttribute(mma_gemm_k, cudaFuncAttributeMaxDynamicSharedMemorySize, S_TOTAL);

    const int* esrc = edge_index;
    const int* edst = edge_index + NEDGES;

    precompute_k<<<17, 256>>>(W_geo, b_geo, emb, W_lot, b_lot);
    wsplit_k<<<dim3(8, 16, 3), dim3(32, 8)>>>(W_mp[0], W_mp[1], W_mp[2]);
    node_init_k<<<NNODES, 256>>>(geometry, semantic, W_lot);

    for (int r = 0; r < 3; r++) {
        gather_seg_k<<<BGR, 256>>>(h, Ahp, Alp, esrc, edst, r);
        mma_gemm_k<<<dim3(2, NNODES / 128), 256, S_TOTAL>>>(
            Ahp, Alp, Wth + (size_t)r * 131072, Wtl + (size_t)r * 131072,
            b_mp[r], cnt, h);
    }
    segmax_k<<<BGR, 256>>>(h, 3);

    sgemm64_k<<<dim3(2, BGR / 64), 256>>>(gvec, 1024, W_agg, 256, 1024, b_agg, latent, 256);
    sgemm64_k<<<dim3(2, BGR / 64), 256>>>(latent, 256, W_mu, 256, 256, b_mu, out, 256);
    sgemm64_k<<<dim3(2, BGR / 64), 256>>>(latent, 256, W_var, 256, 256, b_var, out + (size_t)BGR * D, 256);
}

// round 9
// speedup vs baseline: 2.4523x; 1.0825x over previous
#include <cuda_runtime.h>
#include <cuda_bf16.h>
#include <cstdint>
#include <cstddef>

#define D 256
#define NB 30
#define BGR 2048
#define NNODES (BGR * NB)      // 61440
#define EPG 240
#define NEDGES (BGR * EPG)     // 491520

// ---------------- device scratch (allocation-free rule) ----------------
__device__ float g_h[(size_t)NNODES * D];        // current node features fp32
__device__ __nv_bfloat16 g_Ah[(size_t)NNODES * 512];
__device__ __nv_bfloat16 g_Al[(size_t)NNODES * 512];
__device__ float g_cnt[NNODES];
__device__ __nv_bfloat16 g_Gh[(size_t)BGR * 1024];   // split graph vector
__device__ __nv_bfloat16 g_Gl[(size_t)BGR * 1024];
__device__ float g_latent[(size_t)BGR * D];
__device__ float g_Wg[5 * D];
__device__ float g_emb2[11 * D];
__device__ float g_biasT[D];
// split-bf16 transposed weights
__device__ __nv_bfloat16 g_Wth[3 * 256 * 512];   // msgpass [3][N=256][K=512]
__device__ __nv_bfloat16 g_Wtl[3 * 256 * 512];
__device__ __nv_bfloat16 g_Wagg_h[256 * 1024];   // agg [N=256][K=1024]
__device__ __nv_bfloat16 g_Wagg_l[256 * 1024];

// ---------------- helpers ----------------
__device__ __forceinline__ uint32_t smem_u32(const void* p) {
    uint32_t a;
    asm("{ .reg .u64 t; cvta.to.shared.u64 t, %1; cvt.u32.u64 %0, t; }" : "=r"(a) : "l"(p));
    return a;
}

#define LDSM(r, addr) \
    asm volatile("ldmatrix.sync.aligned.m8n8.x4.shared.b16 {%0,%1,%2,%3}, [%4];" \
        : "=r"((r)[0]), "=r"((r)[1]), "=r"((r)[2]), "=r"((r)[3]) : "r"(addr))

#define MMA(d, a, b0_, b1_) \
    asm volatile("mma.sync.aligned.m16n8k16.row.col.f32.bf16.bf16.f32 " \
        "{%0,%1,%2,%3}, {%4,%5,%6,%7}, {%8,%9}, {%0,%1,%2,%3};" \
        : "+f"((d)[0]), "+f"((d)[1]), "+f"((d)[2]), "+f"((d)[3]) \
        : "r"((a)[0]), "r"((a)[1]), "r"((a)[2]), "r"((a)[3]), "r"(b0_), "r"(b1_))

#define CP16(dst, src) \
    asm volatile("cp.async.cg.shared.global [%0], [%1], 16;" :: "r"(dst), "l"(src))
#define CP_COMMIT() asm volatile("cp.async.commit_group;")
#define CP_WAIT1()  asm volatile("cp.async.wait_group 1;")
#define CP_WAIT0()  asm volatile("cp.async.wait_group 0;")

// ---------------------------------------------------------------------------
// Fold input MLP weights
// ---------------------------------------------------------------------------
__global__ void precompute_k(const float* __restrict__ Wgeo,
                             const float* __restrict__ bgeo,
                             const float* __restrict__ emb,
                             const float* __restrict__ Wlot,
                             const float* __restrict__ blot) {
    int row = blockIdx.x;
    int c = threadIdx.x;
    float acc = 0.f;
    if (row < 5) {
        for (int j = 0; j < D; j++) acc += Wgeo[row * D + j] * Wlot[j * D + c];
        g_Wg[row * D + c] = acc;
    } else if (row < 16) {
        int s = row - 5;
        for (int j = 0; j < D; j++) acc += emb[s * D + j] * Wlot[(256 + j) * D + c];
        g_emb2[s * D + c] = acc;
    } else {
        for (int j = 0; j < D; j++) acc += bgeo[j] * Wlot[j * D + c];
        g_biasT[c] = acc + blot[c];
    }
}

// ---------------------------------------------------------------------------
// Generic transpose + bf16-split: Wt[n][k] = W[k][n], W is [K x 256]
// grid (8 n-tiles, K/32 k-tiles), block (32, 8)
// ---------------------------------------------------------------------------
__device__ __forceinline__ void wsplit_tile(const float* __restrict__ W,
                                            __nv_bfloat16* __restrict__ Th,
                                            __nv_bfloat16* __restrict__ Tl,
                                            int ldk) {
    __shared__ float sm[32][33];
    int n0 = blockIdx.x * 32, k0 = blockIdx.y * 32;
    int tx = threadIdx.x, ty = threadIdx.y;
#pragma unroll
    for (int i = 0; i < 4; i++) {
        int k = k0 + ty + i * 8;
        sm[ty + i * 8][tx] = W[(size_t)k * 256 + n0 + tx];
    }
    __syncthreads();
#pragma unroll
    for (int i = 0; i < 4; i++) {
        int n = n0 + ty + i * 8;
        float v = sm[tx][ty + i * 8];
        __nv_bfloat16 hi = __float2bfloat16(v);
        __nv_bfloat16 lo = __float2bfloat16(v - __bfloat162float(hi));
        size_t o = (size_t)n * ldk + k0 + tx;
        Th[o] = hi;
        Tl[o] = lo;
    }
}

__global__ void wsplit_mp_k(const float* __restrict__ W0,
                            const float* __restrict__ W1,
                            const float* __restrict__ W2) {
    int m = blockIdx.z;
    const float* W = (m == 0) ? W0 : (m == 1) ? W1 : W2;
    wsplit_tile(W, g_Wth + (size_t)m * 131072, g_Wtl + (size_t)m * 131072, 512);
}

__global__ void wsplit_agg_k(const float* __restrict__ Wagg) {
    wsplit_tile(Wagg, g_Wagg_h, g_Wagg_l, 1024);
}

// ---------------------------------------------------------------------------
// h0 = relu(geometry@Wg + emb2[sem] + Wpos[pos] + biasT)
// ---------------------------------------------------------------------------
__global__ void node_init_k(const float* __restrict__ geom,
                            const int* __restrict__ sem,
                            const float* __restrict__ Wlot) {
    int node = blockIdx.x;
    int c = threadIdx.x;
    int pos = node % NB;
    int s = sem[node];
    float acc = g_biasT[c] + g_emb2[s * D + c] + Wlot[(512 + pos) * D + c];
#pragma unroll
    for (int k = 0; k < 5; k++) acc += geom[node * 5 + k] * g_Wg[k * D + c];
    g_h[(size_t)node * D + c] = fmaxf(acc, 0.f);
}

// ---------------------------------------------------------------------------
// Standalone segmax (final phase) -> split graph vector
// ---------------------------------------------------------------------------
__global__ void segmax_k(const float* __restrict__ h, int phase) {
    int b = blockIdx.x;
    int c = threadIdx.x;
    const float* p = h + (size_t)b * NB * D + c;
    float m = -1e30f;
#pragma unroll
    for (int r = 0; r < NB; r++) m = fmaxf(m, p[(size_t)r * D]);
    __nv_bfloat16 hi = __float2bfloat16(m);
    __nv_bfloat16 lo = __float2bfloat16(m - __bfloat162float(hi));
    g_Gh[(size_t)b * 1024 + phase * D + c] = hi;
    g_Gl[(size_t)b * 1024 + phase * D + c] = lo;
}

// ---------------------------------------------------------------------------
// Fused gather + segmax + split-bf16 operand production.
// ---------------------------------------------------------------------------
__global__ void gather_seg_k(const float* __restrict__ h,
                             __nv_bfloat16* __restrict__ Ah,
                             __nv_bfloat16* __restrict__ Al,
                             const int* __restrict__ esrc,
                             const int* __restrict__ edst,
                             int phase) {
    __shared__ float hb[NB * D];     // 30 KB
    __shared__ float cnt_s[NB], inv_s[NB];
    __shared__ int start_s[NB + 1], pos_s[NB];
    __shared__ int srt[EPG], ed_s[EPG], ed_d[EPG];
    int b = blockIdx.x, t = threadIdx.x;

    const float* base = h + (size_t)b * NB * D + t;
    float m = -1e30f;
#pragma unroll
    for (int r = 0; r < NB; r++) {
        float v = base[(size_t)r * D];
        hb[r * D + t] = v;
        m = fmaxf(m, v);
        __nv_bfloat16 hi = __float2bfloat16(v);
        __nv_bfloat16 lo = __float2bfloat16(v - __bfloat162float(hi));
        size_t row = (size_t)(b * NB + r) * 512;
        Ah[row + t] = hi;
        Al[row + t] = lo;
    }
    {
        __nv_bfloat16 hi = __float2bfloat16(m);
        __nv_bfloat16 lo = __float2bfloat16(m - __bfloat162float(hi));
        g_Gh[(size_t)b * 1024 + phase * D + t] = hi;
        g_Gl[(size_t)b * 1024 + phase * D + t] = lo;
    }
    if (t < NB) cnt_s[t] = 0.f;
    __syncthreads();
    if (t < EPG) {
        int s = esrc[(size_t)b * EPG + t] - b * NB;
        int d0 = edst[(size_t)b * EPG + t] - b * NB;
        ed_s[t] = s;
        ed_d[t] = d0;
        atomicAdd(&cnt_s[d0], 1.f);
    }
    __syncthreads();
    if (t == 0) {
        int acc = 0;
        for (int r = 0; r < NB; r++) {
            start_s[r] = acc;
            pos_s[r] = acc;
            acc += (int)cnt_s[r];
        }
        start_s[NB] = acc;
    }
    __syncthreads();
    if (t < EPG) {
        int idx = atomicAdd(&pos_s[ed_d[t]], 1);
        srt[idx] = ed_s[t];
    }
    if (t < NB) {
        float c = cnt_s[t];
        inv_s[t] = (c > 0.f) ? 1.f / c : 0.f;
        g_cnt[b * NB + t] = c;
    }
    __syncthreads();

    for (int r = 0; r < NB; r++) {
        float acc = 0.f;
        int e0 = start_s[r], e1 = start_s[r + 1];
        for (int j = e0; j < e1; j++) acc += hb[srt[j] * D + t];
        float v = acc * inv_s[r];
        __nv_bfloat16 hi = __float2bfloat16(v);
        __nv_bfloat16 lo = __float2bfloat16(v - __bfloat162float(hi));
        size_t row = (size_t)(b * NB + r) * 512;
        Ah[row + 256 + t] = hi;
        Al[row + 256 + t] = lo;
    }
}

// ---------------------------------------------------------------------------
// Split-bf16 tensor-core GEMM via mma.sync + cp.async double buffering.
// CTA: 64 M x 256 N, 8 warps (2 M-warps x 4 N-warps), K chunked by 32.
// Stage = 50KB, 2 stages = 100KB -> 2 CTAs/SM.
// C[M,256] = [mask*][relu](A[M,lda] @ Wt^T + bias)
// ---------------------------------------------------------------------------
#define KC 32
#define RSTRIDE 80                   // 64B row + 16B pad
#define OFF_AH 0
#define OFF_AL 5120
#define OFF_WH 10240
#define OFF_WL 30720
#define S_STAGE 51200
#define S_TOTAL (2 * S_STAGE)        // 102400

__device__ __forceinline__ void stage_load(uint32_t base,
                                           const __nv_bfloat16* __restrict__ Ah,
                                           const __nv_bfloat16* __restrict__ Al,
                                           const __nv_bfloat16* __restrict__ Wh,
                                           const __nv_bfloat16* __restrict__ Wl,
                                           int brow, int k0, int lda, int tid) {
    // A: 64 rows x 32 bf16, one CP16 per thread per buffer
    {
        int r = tid >> 2, c = tid & 3;
        uint32_t doff = (uint32_t)(r * RSTRIDE + c * 16);
        size_t ga = (size_t)(brow + r) * lda + k0 + c * 8;
        CP16(base + OFF_AH + doff, Ah + ga);
        CP16(base + OFF_AL + doff, Al + ga);
    }
    // W: 256 rows x 32 bf16
#pragma unroll
    for (int i = 0; i < 4; i++) {
        int n = i * 64 + (tid >> 2), c = tid & 3;
        uint32_t doff = (uint32_t)(n * RSTRIDE + c * 16);
        size_t gw = (size_t)n * lda + k0 + c * 8;
        CP16(base + OFF_WH + doff, Wh + gw);
        CP16(base + OFF_WL + doff, Wl + gw);
    }
}

template <int RELU, int MASK>
__global__ void __launch_bounds__(256, 2)
mma_gemm_k(const __nv_bfloat16* __restrict__ Ah,
           const __nv_bfloat16* __restrict__ Al,
           const __nv_bfloat16* __restrict__ Wh,
           const __nv_bfloat16* __restrict__ Wl,
           const float* __restrict__ bias,
           const float* __restrict__ cnt,
           float* __restrict__ C, int lda) {
    extern __shared__ char smem[];
    uint32_t sb = smem_u32(smem);
    int tid = threadIdx.x;
    int lane = tid & 31, wid = tid >> 5;
    int brow = blockIdx.x * 64;
    int wm = wid & 1;          // 2 M-warps -> 32 rows each
    int wn = wid >> 1;         // 4 N-warps -> 64 cols each
    int nchunk = lda >> 5;

    float acc[2][8][4];
#pragma unroll
    for (int i = 0; i < 2; i++)
#pragma unroll
        for (int j = 0; j < 8; j++)
#pragma unroll
            for (int q = 0; q < 4; q++) acc[i][j][q] = 0.f;

    uint32_t aOff = (uint32_t)((wm * 32 + (lane & 15)) * RSTRIDE + (lane >> 4) * 16);
    int bq = lane >> 3;
    uint32_t bOff = (uint32_t)((wn * 64 + (lane & 7) + (bq & 2) * 4) * RSTRIDE + (bq & 1) * 16);

    stage_load(sb, Ah, Al, Wh, Wl, brow, 0, lda, tid);
    CP_COMMIT();

    for (int c = 0; c < nchunk; c++) {
        uint32_t cur = sb + (uint32_t)(c & 1) * S_STAGE;
        if (c < nchunk - 1) {
            stage_load(sb + (uint32_t)((c + 1) & 1) * S_STAGE, Ah, Al, Wh, Wl,
                       brow, (c + 1) * KC, lda, tid);
            CP_COMMIT();
            CP_WAIT1();
        } else {
            CP_WAIT0();
        }
        __syncthreads();

        uint32_t aBase = cur + aOff;
        uint32_t bBase = cur + bOff;
#pragma unroll
        for (int ks = 0; ks < 2; ks++) {
            uint32_t ah[2][4], al[2][4];
#pragma unroll
            for (int mt = 0; mt < 2; mt++) {
                uint32_t addr = aBase + mt * (16 * RSTRIDE) + ks * 32;
                LDSM(ah[mt], addr + OFF_AH);
                LDSM(al[mt], addr + OFF_AL);
            }
#pragma unroll
            for (int np = 0; np < 4; np++) {
                uint32_t bh[4], bl[4];
                uint32_t addr = bBase + np * (16 * RSTRIDE) + ks * 32;
                LDSM(bh, addr + OFF_WH);
                LDSM(bl, addr + OFF_WL);
#pragma unroll
                for (int mt = 0; mt < 2; mt++) {
                    MMA(acc[mt][2 * np],     ah[mt], bh[0], bh[1]);
                    MMA(acc[mt][2 * np],     al[mt], bh[0], bh[1]);
                    MMA(acc[mt][2 * np],     ah[mt], bl[0], bl[1]);
                    MMA(acc[mt][2 * np + 1], ah[mt], bh[2], bh[3]);
                    MMA(acc[mt][2 * np + 1], al[mt], bh[2], bh[3]);
                    MMA(acc[mt][2 * np + 1], ah[mt], bl[2], bl[3]);
                }
            }
        }
        __syncthreads();
    }

    // epilogue: bias [+relu] [+cnt-mask], direct STG.64
#pragma unroll
    for (int mt = 0; mt < 2; mt++) {
        int r1 = brow + wm * 32 + mt * 16 + (lane >> 2);
        int r2 = r1 + 8;
        float k1 = 1.f, k2 = 1.f;
        if (MASK) {
            k1 = (cnt[r1] > 0.f) ? 1.f : 0.f;
            k2 = (cnt[r2] > 0.f) ? 1.f : 0.f;
        }
#pragma unroll
        for (int nt = 0; nt < 8; nt++) {
            int cc = wn * 64 + nt * 8 + (lane & 3) * 2;
            float bx = bias[cc], by = bias[cc + 1];
            float2 v1, v2;
            v1.x = acc[mt][nt][0] + bx; v1.y = acc[mt][nt][1] + by;
            v2.x = acc[mt][nt][2] + bx; v2.y = acc[mt][nt][3] + by;
            if (RELU) {
                v1.x = fmaxf(v1.x, 0.f); v1.y = fmaxf(v1.y, 0.f);
                v2.x = fmaxf(v2.x, 0.f); v2.y = fmaxf(v2.y, 0.f);
            }
            if (MASK) {
                v1.x *= k1; v1.y *= k1;
                v2.x *= k2; v2.y *= k2;
            }
            *(float2*)(C + (size_t)r1 * D + cc) = v1;
            *(float2*)(C + (size_t)r2 * D + cc) = v2;
        }
    }
}

// ---------------------------------------------------------------------------
// fp32 SGEMM, 64x128 tile (small head GEMMs: mu / var)
// ---------------------------------------------------------------------------
__global__ void sgemm64_k(const float* __restrict__ A, int lda,
                          const float* __restrict__ B, int N, int K,
                          const float* __restrict__ bias,
                          float* __restrict__ C, int ldc) {
    __shared__ float As[8][64];
    __shared__ float Bs[8][128];
    int tid = threadIdx.x;
    int brow = blockIdx.y * 64;
    int bcol = blockIdx.x * 128;
    int a_r = tid >> 2, a_c = (tid & 3) * 2;
    int b_r = tid >> 5, b_c = (tid & 31) * 4;
    int ty = tid >> 4, tx = tid & 15;
    float acc[4][8] = {};
    const float* Aptr = A + (size_t)(brow + a_r) * lda + a_c;
    const float* Bptr = B + (size_t)b_r * N + bcol + b_c;
    for (int k0 = 0; k0 < K; k0 += 8) {
        float2 av = *(const float2*)(Aptr + k0);
        float4 bv = *(const float4*)(Bptr + (size_t)k0 * N);
        As[a_c + 0][a_r] = av.x;
        As[a_c + 1][a_r] = av.y;
        *(float4*)&Bs[b_r][b_c] = bv;
        __syncthreads();
#pragma unroll
        for (int k = 0; k < 8; k++) {
            float ar[4], br[8];
            *(float4*)(ar) = *(const float4*)&As[k][ty * 4];
            *(float4*)(br) = *(const float4*)&Bs[k][tx * 8];
            *(float4*)(br + 4) = *(const float4*)&Bs[k][tx * 8 + 4];
#pragma unroll
            for (int i = 0; i < 4; i++)
#pragma unroll
                for (int j = 0; j < 8; j++) acc[i][j] += ar[i] * br[j];
        }
        __syncthreads();
    }
    float4 bv0 = *(const float4*)&bias[bcol + tx * 8];
    float4 bv1 = *(const float4*)&bias[bcol + tx * 8 + 4];
#pragma unroll
    for (int i = 0; i < 4; i++) {
        int r = brow + ty * 4 + i;
        float4 v0, v1;
        v0.x = acc[i][0] + bv0.x; v0.y = acc[i][1] + bv0.y;
        v0.z = acc[i][2] + bv0.z; v0.w = acc[i][3] + bv0.w;
        v1.x = acc[i][4] + bv1.x; v1.y = acc[i][5] + bv1.y;
        v1.z = acc[i][6] + bv1.z; v1.w = acc[i][7] + bv1.w;
        *(float4*)&C[(size_t)r * ldc + bcol + tx * 8] = v0;
        *(float4*)&C[(size_t)r * ldc + bcol + tx * 8 + 4] = v1;
    }
}

extern "C" void kernel_launch(void* const* d_in, const int* in_sizes, int n_in,
                              void* d_out, int out_size) {
    (void)in_sizes; (void)n_in; (void)out_size;
    const float* geometry = (const float*)d_in[0];
    const int*   semantic = (const int*)d_in[1];
    const int*   edge_index = (const int*)d_in[2];
    const float* W_geo = (const float*)d_in[4];
    const float* b_geo = (const float*)d_in[5];
    const float* emb   = (const float*)d_in[6];
    const float* W_lot = (const float*)d_in[7];
    const float* b_lot = (const float*)d_in[8];
    const float* W_mp[3] = {(const float*)d_in[9], (const float*)d_in[11], (const float*)d_in[13]};
    const float* b_mp[3] = {(const float*)d_in[10], (const float*)d_in[12], (const float*)d_in[14]};
    const float* W_agg = (const float*)d_in[15];
    const float* b_agg = (const float*)d_in[16];
    const float* W_mu  = (const float*)d_in[17];
    const float* b_mu  = (const float*)d_in[18];
    const float* W_var = (const float*)d_in[19];
    const float* b_var = (const float*)d_in[20];
    float* out = (float*)d_out;

    float *h, *cnt, *latent;
    __nv_bfloat16 *Ahp, *Alp, *Wth, *Wtl, *Gh, *Gl, *Wah, *Wal;
    cudaGetSymbolAddress((void**)&h, g_h);
    cudaGetSymbolAddress((void**)&Ahp, g_Ah);
    cudaGetSymbolAddress((void**)&Alp, g_Al);
    cudaGetSymbolAddress((void**)&cnt, g_cnt);
    cudaGetSymbolAddress((void**)&latent, g_latent);
    cudaGetSymbolAddress((void**)&Wth, g_Wth);
    cudaGetSymbolAddress((void**)&Wtl, g_Wtl);
    cudaGetSymbolAddress((void**)&Gh, g_Gh);
    cudaGetSymbolAddress((void**)&Gl, g_Gl);
    cudaGetSymbolAddress((void**)&Wah, g_Wagg_h);
    cudaGetSymbolAddress((void**)&Wal, g_Wagg_l);

    cudaFuncSetAttribute(mma_gemm_k<1, 1>, cudaFuncAttributeMaxDynamicSharedMemorySize, S_TOTAL);
    cudaFuncSetAttribute(mma_gemm_k<0, 0>, cudaFuncAttributeMaxDynamicSharedMemorySize, S_TOTAL);

    const int* esrc = edge_index;
    const int* edst = edge_index + NEDGES;

    // launches 1-4 (so launch #6 = first mma_gemm_k -> captured by ncu -s 5 -c 1)
    precompute_k<<<17, 256>>>(W_geo, b_geo, emb, W_lot, b_lot);
    wsplit_mp_k<<<dim3(8, 16, 3), dim3(32, 8)>>>(W_mp[0], W_mp[1], W_mp[2]);
    wsplit_agg_k<<<dim3(8, 32), dim3(32, 8)>>>(W_agg);
    node_init_k<<<NNODES, 256>>>(geometry, semantic, W_lot);

    for (int r = 0; r < 3; r++) {
        gather_seg_k<<<BGR, 256>>>(h, Ahp, Alp, esrc, edst, r);
        mma_gemm_k<1, 1><<<NNODES / 64, 256, S_TOTAL>>>(
            Ahp, Alp, Wth + (size_t)r * 131072, Wtl + (size_t)r * 131072,
            b_mp[r], cnt, h, 512);
    }
    segmax_k<<<BGR, 256>>>(h, 3);

    // head: latent = G @ W_agg + b_agg via split-bf16 mma (K=1024)
    mma_gemm_k<0, 0><<<BGR / 64, 256, S_TOTAL>>>(
        Gh, Gl, Wah, Wal, b_agg, nullptr, latent, 1024);
    sgemm64_k<<<dim3(2, BGR / 64), 256>>>(latent, 256, W_mu, 256, 256, b_mu, out, 256);
    sgemm64_k<<<dim3(2, BGR / 64), 256>>>(latent, 256, W_var, 256, 256, b_var, out + (size_t)BGR * D, 256);
}